// round 1
// baseline (speedup 1.0000x reference)
#include <cuda_runtime.h>
#include <cuda_bf16.h>

// Problem constants (reference: N=100000 nodes, F=128 feats, HID=32)
#define FEAT 128
#define HID  32
#define NCOL 64          // 32 z-columns + 32 h-columns, fused
#define TPB  256

// Precombined gate weights: g_W[k*64 + j], j<32 -> Wz_eff[k][j], j>=32 -> Wh_eff[k][j-32]
__device__ __align__(16) float g_W[FEAT * NCOL];

// W has shape (2,1,160,32); index [s,0,k,j] = s*5120 + k*32 + j. Only k<128 live (H0=0).
__global__ void prep_kernel(const float* __restrict__ Wz, const float* __restrict__ Wh) {
    int idx = blockIdx.x * blockDim.x + threadIdx.x;   // 0..8191
    if (idx >= FEAT * NCOL) return;
    int k = idx >> 6;
    int j = idx & 63;
    const float* W = (j < HID) ? Wz : Wh;
    int jj = j & (HID - 1);
    g_W[idx] = W[k * HID + jj] + W[5120 + k * HID + jj];
}

__device__ __forceinline__ unsigned long long pack2(float v) {
    unsigned long long r;
    asm("mov.b64 %0, {%1, %1};" : "=l"(r) : "f"(v));
    return r;
}
__device__ __forceinline__ void fma2(unsigned long long& acc, unsigned long long a,
                                     unsigned long long b) {
    asm("fma.rn.f32x2 %0, %1, %2, %0;" : "+l"(acc) : "l"(a), "l"(b));
}
__device__ __forceinline__ void unpack2(unsigned long long v, float& lo, float& hi) {
    asm("mov.b64 {%0, %1}, %2;" : "=f"(lo), "=f"(hi) : "l"(v));
}

__device__ __forceinline__ float sigmoid_f(float v) {
    return __fdividef(1.0f, 1.0f + __expf(-v));
}
__device__ __forceinline__ float tanh_f(float v) {
    // tanh(v) = 1 - 2/(e^{2v}+1); saturates correctly at +/-inf
    return 1.0f - __fdividef(2.0f, __expf(2.0f * v) + 1.0f);
}

__global__ void __launch_bounds__(TPB, 2)
dcrnn_kernel(const float* __restrict__ x,
             const float* __restrict__ bz, const float* __restrict__ bh,
             const float* __restrict__ wlin, const float* __restrict__ blin,
             float* __restrict__ out, int nNodes)
{
    __shared__ __align__(16) float sW[FEAT * NCOL];   // 32 KB
    __shared__ float sBz[HID], sBh[HID], sWl[HID], sBl;

    // Cooperative stage of the fused weight matrix (L2-resident after first wave)
    {
        const float4* src = (const float4*)g_W;
        float4*       dst = (float4*)sW;
        #pragma unroll
        for (int i = 0; i < (FEAT * NCOL / 4) / TPB; i++)   // 2048/256 = 8
            dst[threadIdx.x + i * TPB] = src[threadIdx.x + i * TPB];
        if (threadIdx.x < HID) {
            sBz[threadIdx.x] = bz[threadIdx.x];
            sBh[threadIdx.x] = bh[threadIdx.x];
            sWl[threadIdx.x] = wlin[threadIdx.x];
        }
        if (threadIdx.x == 0) sBl = blin[0];
    }
    __syncthreads();

    int node = blockIdx.x * TPB + threadIdx.x;
    bool active = (node < nNodes);

    // 16 packed accumulators per gate: accz[p] = (dot_z[2p], dot_z[2p+1])
    unsigned long long accz[16], acch[16];
    #pragma unroll
    for (int p = 0; p < 16; p++) { accz[p] = 0ull; acch[p] = 0ull; }

    const float4* xrow = (const float4*)(x + (size_t)(active ? node : 0) * FEAT);

    #pragma unroll 4
    for (int kq = 0; kq < FEAT / 4; kq++) {
        float4 xv = xrow[kq];                    // LDG.128, own row (L1-line reuse over kq)
        #pragma unroll
        for (int s = 0; s < 4; s++) {
            float xk = (s == 0) ? xv.x : (s == 1) ? xv.y : (s == 2) ? xv.z : xv.w;
            unsigned long long xx = pack2(xk);
            int k = kq * 4 + s;
            const ulonglong2* zr = (const ulonglong2*)(sW + k * NCOL);        // 32 z floats
            const ulonglong2* hr = (const ulonglong2*)(sW + k * NCOL + HID);  // 32 h floats
            #pragma unroll
            for (int q = 0; q < 8; q++) {        // 8 x LDS.128 (broadcast) -> 16 FFMA2
                ulonglong2 wz = zr[q];
                fma2(accz[2 * q + 0], xx, wz.x);
                fma2(accz[2 * q + 1], xx, wz.y);
            }
            #pragma unroll
            for (int q = 0; q < 8; q++) {
                ulonglong2 wh = hr[q];
                fma2(acch[2 * q + 0], xx, wh.x);
                fma2(acch[2 * q + 1], xx, wh.y);
            }
        }
    }

    if (active) {
        float res = sBl;
        #pragma unroll
        for (int p = 0; p < 16; p++) {
            float z0, z1, h0, h1;
            unpack2(accz[p], z0, z1);
            unpack2(acch[p], h0, h1);
            int j0 = 2 * p, j1 = 2 * p + 1;
            {
                float z  = sigmoid_f(z0 + sBz[j0]);
                float ht = tanh_f(h0 + sBh[j0]);
                float g  = fmaxf((1.0f - z) * ht, 0.0f);
                res = fmaf(g, sWl[j0], res);
            }
            {
                float z  = sigmoid_f(z1 + sBz[j1]);
                float ht = tanh_f(h1 + sBh[j1]);
                float g  = fmaxf((1.0f - z) * ht, 0.0f);
                res = fmaf(g, sWl[j1], res);
            }
        }
        out[node] = res;
    }
}

// Inputs (metadata order):
// 0:x[N*128] f32   1:edge_index[2*E] i64 (dead)   2:edge_weight[E] f32 (dead)
// 3:W_z[10240]     4:b_z[32]   5:W_r (dead)   6:b_r (dead)
// 7:W_h[10240]     8:b_h[32]   9:W_lin[32]   10:b_lin[1]
extern "C" void kernel_launch(void* const* d_in, const int* in_sizes, int n_in,
                              void* d_out, int out_size) {
    const float* x     = (const float*)d_in[0];
    const float* W_z   = (const float*)d_in[3];
    const float* b_z   = (const float*)d_in[4];
    const float* W_h   = (const float*)d_in[7];
    const float* b_h   = (const float*)d_in[8];
    const float* W_lin = (const float*)d_in[9];
    const float* b_lin = (const float*)d_in[10];
    float* out = (float*)d_out;

    int nNodes = out_size;                       // one scalar per node

    prep_kernel<<<(FEAT * NCOL + TPB - 1) / TPB, TPB>>>(W_z, W_h);
    dcrnn_kernel<<<(nNodes + TPB - 1) / TPB, TPB>>>(x, b_z, b_h, W_lin, b_lin, out, nNodes);
}

// round 2
// speedup vs baseline: 1.0013x; 1.0013x over previous
#include <cuda_runtime.h>
#include <cuda_bf16.h>

#define FEAT 128
#define HID  32
#define NCOL 64          // 32 z + 32 h fused columns
#define TPB  256
#define NODES_PER_BLOCK 256   // 64 groups * 4 nodes

// Interleaved fused weights: row k, quarter q (0..3) holds
//   [z_{8q}..z_{8q+7}, h_{8q}..h_{8q+7}]  (16 floats per quarter)
__device__ __align__(16) float g_W[FEAT * NCOL];

// W tensors have shape (2,1,160,32); [s,0,k,j] = s*5120 + k*32 + j. Only k<128 live (H0=0).
__global__ void prep_kernel(const float* __restrict__ Wz, const float* __restrict__ Wh) {
    int idx = blockIdx.x * blockDim.x + threadIdx.x;   // 0..8191
    if (idx >= FEAT * NCOL) return;
    int k = idx >> 6;
    int j = idx & 63;
    int q = j >> 4;          // quarter
    int c = j & 15;          // pos in quarter
    int jj = q * 8 + (c & 7);                 // actual gate column 0..31
    const float* W = (c < 8) ? Wz : Wh;
    g_W[idx] = W[k * HID + jj] + W[5120 + k * HID + jj];
}

__device__ __forceinline__ unsigned long long pack2(float v) {
    unsigned long long r;
    asm("mov.b64 %0, {%1, %1};" : "=l"(r) : "f"(v));
    return r;
}
__device__ __forceinline__ void fma2(unsigned long long& acc, unsigned long long a,
                                     unsigned long long b) {
    asm("fma.rn.f32x2 %0, %1, %2, %0;" : "+l"(acc) : "l"(a), "l"(b));
}
__device__ __forceinline__ void unpack2(unsigned long long v, float& lo, float& hi) {
    asm("mov.b64 {%0, %1}, %2;" : "=f"(lo), "=f"(hi) : "l"(v));
}
__device__ __forceinline__ float sigmoid_f(float v) {
    return __fdividef(1.0f, 1.0f + __expf(-v));
}
__device__ __forceinline__ float tanh_f(float v) {
    return 1.0f - __fdividef(2.0f, __expf(2.0f * v) + 1.0f);
}

__global__ void __launch_bounds__(TPB, 2)
dcrnn_kernel(const float* __restrict__ x,
             const float* __restrict__ bz, const float* __restrict__ bh,
             const float* __restrict__ wlin, const float* __restrict__ blin,
             float* __restrict__ out, int nNodes)
{
    __shared__ __align__(16) float sW[FEAT * NCOL];   // 32 KB
    __shared__ float sBz[HID], sBh[HID], sWl[HID], sBl;

    {
        const float4* src = (const float4*)g_W;
        float4*       dst = (float4*)sW;
        #pragma unroll
        for (int i = 0; i < (FEAT * NCOL / 4) / TPB; i++)     // 8
            dst[threadIdx.x + i * TPB] = src[threadIdx.x + i * TPB];
        if (threadIdx.x < HID) {
            sBz[threadIdx.x] = bz[threadIdx.x];
            sBh[threadIdx.x] = bh[threadIdx.x];
            sWl[threadIdx.x] = wlin[threadIdx.x];
        }
        if (threadIdx.x == 0) sBl = blin[0];
    }
    __syncthreads();

    const int g  = threadIdx.x >> 2;       // 0..63 node group
    const int jq = threadIdx.x & 3;        // column quarter
    const int node0 = blockIdx.x * NODES_PER_BLOCK + g * 4;

    // Per-node row pointers (clamped for tail safety)
    const float4* xr[4];
    #pragma unroll
    for (int n = 0; n < 4; n++) {
        int nd = node0 + n;
        xr[n] = (const float4*)(x + (size_t)(nd < nNodes ? nd : 0) * FEAT);
    }

    // accz[n][p]/acch[n][p]: packed pair for thread-local cols (2p, 2p+1), node n
    unsigned long long accz[4][4], acch[4][4];
    #pragma unroll
    for (int n = 0; n < 4; n++)
        #pragma unroll
        for (int p = 0; p < 4; p++) { accz[n][p] = 0ull; acch[n][p] = 0ull; }

    const float* wbase = sW + jq * 16;

    #pragma unroll 2
    for (int kq = 0; kq < FEAT / 4; kq++) {
        float xv[4][4];
        #pragma unroll
        for (int n = 0; n < 4; n++)
            *(float4*)xv[n] = xr[n][kq];                // 4x LDG.128

        #pragma unroll
        for (int s = 0; s < 4; s++) {
            const ulonglong2* wr =
                (const ulonglong2*)(wbase + (kq * 4 + s) * NCOL);
            ulonglong2 wz0 = wr[0];   // z cols 0,1,2,3 (thread-local)
            ulonglong2 wz1 = wr[1];   // z cols 4..7
            ulonglong2 wh0 = wr[2];   // h cols 0..3
            ulonglong2 wh1 = wr[3];   // h cols 4..7
            #pragma unroll
            for (int n = 0; n < 4; n++) {
                unsigned long long xx = pack2(xv[n][s]);
                fma2(accz[n][0], xx, wz0.x);
                fma2(accz[n][1], xx, wz0.y);
                fma2(accz[n][2], xx, wz1.x);
                fma2(accz[n][3], xx, wz1.y);
                fma2(acch[n][0], xx, wh0.x);
                fma2(acch[n][1], xx, wh0.y);
                fma2(acch[n][2], xx, wh1.x);
                fma2(acch[n][3], xx, wh1.y);
            }
        }
    }

    // Epilogue: thread-local 8 gate columns -> partial dot with W_lin
    float bzv[8], bhv[8], wlv[8];
    #pragma unroll
    for (int c = 0; c < 8; c++) {
        bzv[c] = sBz[jq * 8 + c];
        bhv[c] = sBh[jq * 8 + c];
        wlv[c] = sWl[jq * 8 + c];
    }

    float res4[4];
    #pragma unroll
    for (int n = 0; n < 4; n++) {
        float partial = 0.0f;
        #pragma unroll
        for (int p = 0; p < 4; p++) {
            float z0, z1, h0, h1;
            unpack2(accz[n][p], z0, z1);
            unpack2(acch[n][p], h0, h1);
            int c0 = 2 * p, c1 = 2 * p + 1;
            {
                float z  = sigmoid_f(z0 + bzv[c0]);
                float ht = tanh_f(h0 + bhv[c0]);
                partial = fmaf(fmaxf((1.0f - z) * ht, 0.0f), wlv[c0], partial);
            }
            {
                float z  = sigmoid_f(z1 + bzv[c1]);
                float ht = tanh_f(h1 + bhv[c1]);
                partial = fmaf(fmaxf((1.0f - z) * ht, 0.0f), wlv[c1], partial);
            }
        }
        // reduce across the 4 column-quarters (adjacent lanes)
        partial += __shfl_xor_sync(0xffffffff, partial, 1);
        partial += __shfl_xor_sync(0xffffffff, partial, 2);
        res4[n] = partial + sBl;
    }

    if (jq == 0) {
        if (node0 + 3 < nNodes) {
            *(float4*)(out + node0) = make_float4(res4[0], res4[1], res4[2], res4[3]);
        } else {
            #pragma unroll
            for (int n = 0; n < 4; n++)
                if (node0 + n < nNodes) out[node0 + n] = res4[n];
        }
    }
}

// Inputs (metadata order):
// 0:x[N*128] f32   1:edge_index (dead)   2:edge_weight (dead)
// 3:W_z[10240]     4:b_z[32]   5:W_r (dead)   6:b_r (dead)
// 7:W_h[10240]     8:b_h[32]   9:W_lin[32]   10:b_lin[1]
extern "C" void kernel_launch(void* const* d_in, const int* in_sizes, int n_in,
                              void* d_out, int out_size) {
    const float* x     = (const float*)d_in[0];
    const float* W_z   = (const float*)d_in[3];
    const float* b_z   = (const float*)d_in[4];
    const float* W_h   = (const float*)d_in[7];
    const float* b_h   = (const float*)d_in[8];
    const float* W_lin = (const float*)d_in[9];
    const float* b_lin = (const float*)d_in[10];
    float* out = (float*)d_out;

    int nNodes = out_size;

    prep_kernel<<<(FEAT * NCOL + TPB - 1) / TPB, TPB>>>(W_z, W_h);
    int blocks = (nNodes + NODES_PER_BLOCK - 1) / NODES_PER_BLOCK;
    dcrnn_kernel<<<blocks, TPB>>>(x, b_z, b_h, W_lin, b_lin, out, nNodes);
}